// round 14
// baseline (speedup 1.0000x reference)
#include <cuda_runtime.h>
#include <cuda_bf16.h>
#include <cuda_fp16.h>
#include <cstdint>

// Problem constants (fixed by the dataset)
#define NN 50000
#define EE 800000
#define DD 128
#define HH 64
#define GG 512
#define NB_SCAN ((NN + 1023) / 1024)   // 49

// ---------------- device scratch (static allocation only) ----------------
__device__ __half g_act[(size_t)NN * DD];  // final-layer activations (for pool)
__device__ __half g_h0[(size_t)NN * DD];   // dinv-scaled GEMM output ping
__device__ __half g_h1[(size_t)NN * DD];   // pong
__device__ float  g_dinv[NN];
__device__ int    g_deg[NN];               // indegree + 1 (self loop)
__device__ int    g_fill[NN];
__device__ int    g_rowptr[NN + 1];
__device__ int    g_csrc[EE];
__device__ int    g_bsum[NB_SCAN];
__device__ int    g_gptr[GG + 1];
__device__ __half g_whi[3 * DD * DD];      // transposed W fp16 hi: [layer][n][k]
__device__ __half g_wlo[3 * DD * DD];      // fp16 lo (residual): W ~= hi + lo

__device__ __forceinline__ uint32_t smem_u32(const void* p) {
    uint32_t a;
    asm("{ .reg .u64 t; cvta.to.shared.u64 t, %1; cvt.u32.u64 %0, t; }"
        : "=r"(a) : "l"(p));
    return a;
}

// ---------------- prep kernels (R12 versions) ----------------
__global__ void k_init_nodes() {
    int i = blockIdx.x * blockDim.x + threadIdx.x;
    if (i < NN) { g_deg[i] = 1; g_fill[i] = 0; }
}

__global__ void k_hist(const int* __restrict__ dst) {
    int e = blockIdx.x * blockDim.x + threadIdx.x;
    if (e < EE) atomicAdd(&g_deg[dst[e]], 1);
}

__global__ void __launch_bounds__(1024) k_scan1() {
    __shared__ int wsum[32];
    int tid = threadIdx.x, lane = tid & 31, wid = tid >> 5;
    int i = blockIdx.x * 1024 + tid;
    int deg = (i < NN) ? g_deg[i] : 1;
    if (i < NN) g_dinv[i] = rsqrtf((float)deg);
    int x = (i < NN) ? (deg - 1) : 0;
    #pragma unroll
    for (int off = 1; off < 32; off <<= 1) {
        int y = __shfl_up_sync(0xffffffff, x, off);
        if (lane >= off) x += y;
    }
    if (lane == 31) wsum[wid] = x;
    __syncthreads();
    if (wid == 0) {
        int w = wsum[lane];
        #pragma unroll
        for (int off = 1; off < 32; off <<= 1) {
            int y = __shfl_up_sync(0xffffffff, w, off);
            if (lane >= off) w += y;
        }
        wsum[lane] = w;
    }
    __syncthreads();
    int incl = x + (wid > 0 ? wsum[wid - 1] : 0);
    if (i < NN) g_rowptr[i + 1] = incl;
    if (tid == 1023) g_bsum[blockIdx.x] = incl;
}

__global__ void __launch_bounds__(1024) k_scan3_gptr(const int* __restrict__ batch) {
    __shared__ int partial[2];
    int tid = threadIdx.x, lane = tid & 31, wid = tid >> 5;
    if (tid < 64) {
        int v = (tid < NB_SCAN && tid < blockIdx.x) ? g_bsum[tid] : 0;
        #pragma unroll
        for (int off = 16; off > 0; off >>= 1)
            v += __shfl_xor_sync(0xffffffffu, v, off);
        if (lane == 0) partial[wid] = v;
    }
    __syncthreads();
    int off = partial[0] + partial[1];
    int i = blockIdx.x * 1024 + tid;
    if (i < NN) {
        g_rowptr[i + 1] += off;
        int b = batch[i];
        int pb = (i > 0) ? batch[i - 1] : -1;
        for (int g = pb + 1; g <= b; g++) g_gptr[g] = i;
        if (i == NN - 1)
            for (int g = b + 1; g <= GG; g++) g_gptr[g] = NN;
    }
    if (i == 0) g_rowptr[0] = 0;
}

__global__ void k_fill(const int* __restrict__ src, const int* __restrict__ dst) {
    int e = blockIdx.x * blockDim.x + threadIdx.x;
    if (e >= EE) return;
    int s = src[e], d = dst[e];
    int p = g_rowptr[d] + atomicAdd(&g_fill[d], 1);
    g_csrc[p] = s;
}

// ---- W conversion only (x handled inside gemm1): hi/lo fp16, transposed ----
#define WBLK (3 * DD * DD / 256)             // 192

__global__ void __launch_bounds__(256) k_convert_w(const float* __restrict__ W1,
                                                   const float* __restrict__ W2,
                                                   const float* __restrict__ W3) {
    int idx = blockIdx.x * 256 + threadIdx.x;   // 0 .. 49151
    int layer = idx >> 14;
    int r = idx & 16383;
    int k = r >> 7, n = r & 127;
    const float* W = (layer == 0) ? W1 : (layer == 1) ? W2 : W3;
    float v = W[k * DD + n];                    // coalesced over n
    __half h = __float2half_rn(v);
    __half l = __float2half_rn(v - __half2float(h));
    g_whi[layer * DD * DD + n * DD + k] = h;
    g_wlo[layer * DD * DD + n * DD + k] = l;
}

// ---------------- shared GEMM core ----------------
// smem A tile already filled by caller. Fills B hi/lo, syncs, runs the
// 2-product fp16 mainloop, writes dinv-scaled fp16 rows to `out`.
#define ASTR 136
#define AS_OFF 0
#define BH_OFF (128 * ASTR)
#define BL_OFF (2 * 128 * ASTR)
#define GSMEM_BYTES (3 * 128 * ASTR * 2)   // 104448

__device__ __forceinline__ void ldsm_x4(uint32_t& r0, uint32_t& r1,
                                        uint32_t& r2, uint32_t& r3, uint32_t a) {
    asm volatile("ldmatrix.sync.aligned.m8n8.x4.shared.b16 {%0,%1,%2,%3}, [%4];"
                 : "=r"(r0), "=r"(r1), "=r"(r2), "=r"(r3) : "r"(a));
}

__device__ __forceinline__ void mma_fp16(float* d, const uint32_t* a,
                                         const uint32_t* b) {
    asm volatile(
        "mma.sync.aligned.m16n8k16.row.col.f32.f16.f16.f32 "
        "{%0,%1,%2,%3}, {%4,%5,%6,%7}, {%8,%9}, {%0,%1,%2,%3};"
        : "+f"(d[0]), "+f"(d[1]), "+f"(d[2]), "+f"(d[3])
        : "r"(a[0]), "r"(a[1]), "r"(a[2]), "r"(a[3]), "r"(b[0]), "r"(b[1]));
}

__device__ __forceinline__ void gemm_core(__half* sm, int row0,
                                          const __half* whi, const __half* wlo,
                                          __half* out) {
    int tid = threadIdx.x;
    int wid = tid >> 5, lane = tid & 31;

    // ---- fill B hi/lo planes ----
    for (int t = tid; t < 2048; t += 512) {
        int q = t & 15, n = t >> 4;
        *(uint4*)&sm[BH_OFF + n * ASTR + q * 8] = *(const uint4*)&whi[n * DD + q * 8];
        *(uint4*)&sm[BL_OFF + n * ASTR + q * 8] = *(const uint4*)&wlo[n * DD + q * 8];
    }
    __syncthreads();

    int wm = (wid >> 2) * 32;
    int wn = (wid & 3) * 32;

    float d[2][4][4];
    #pragma unroll
    for (int i = 0; i < 2; i++)
        #pragma unroll
        for (int j = 0; j < 4; j++)
            #pragma unroll
            for (int r = 0; r < 4; r++) d[i][j][r] = 0.f;

    uint32_t sbase = smem_u32(sm);

    #pragma unroll
    for (int kc = 0; kc < 8; kc++) {
        int k0 = kc * 16;
        uint32_t ah[2][4], bh[4][2], bl[4][2];
        #pragma unroll
        for (int i = 0; i < 2; i++) {
            int r = wm + 16 * i + (lane & 15);
            int c = k0 + (lane >> 4) * 8;
            uint32_t ad = sbase + (uint32_t)(AS_OFF + r * ASTR + c) * 2;
            ldsm_x4(ah[i][0], ah[i][1], ah[i][2], ah[i][3], ad);
        }
        #pragma unroll
        for (int jj = 0; jj < 2; jj++) {
            int n = wn + 16 * jj + (lane & 15);
            int c = k0 + (lane >> 4) * 8;
            uint32_t r0, r1, r2, r3;
            uint32_t ad = sbase + (uint32_t)(BH_OFF + n * ASTR + c) * 2;
            ldsm_x4(r0, r1, r2, r3, ad);
            bh[2 * jj][0] = r0; bh[2 * jj + 1][0] = r1;
            bh[2 * jj][1] = r2; bh[2 * jj + 1][1] = r3;
            ad = sbase + (uint32_t)(BL_OFF + n * ASTR + c) * 2;
            ldsm_x4(r0, r1, r2, r3, ad);
            bl[2 * jj][0] = r0; bl[2 * jj + 1][0] = r1;
            bl[2 * jj][1] = r2; bl[2 * jj + 1][1] = r3;
        }
        #pragma unroll
        for (int i = 0; i < 2; i++)
            #pragma unroll
            for (int j = 0; j < 4; j++) {
                mma_fp16(d[i][j], ah[i], bh[j]);
                mma_fp16(d[i][j], ah[i], bl[j]);
            }
    }

    // ---- epilogue: scale by dinv[row], fp32 -> fp16 out ----
    int rr = lane >> 2;
    int cc = 2 * (lane & 3);
    #pragma unroll
    for (int i = 0; i < 2; i++) {
        int r_lo = row0 + wm + 16 * i + rr;
        int r_hi = r_lo + 8;
        float di_lo = (r_lo < NN) ? g_dinv[r_lo] : 0.f;
        float di_hi = (r_hi < NN) ? g_dinv[r_hi] : 0.f;
        #pragma unroll
        for (int j = 0; j < 4; j++) {
            int col = wn + 8 * j + cc;
            if (r_lo < NN) {
                __half2 h = __floats2half2_rn(d[i][j][0] * di_lo, d[i][j][1] * di_lo);
                *(__half2*)&out[(size_t)r_lo * DD + col] = h;
            }
            if (r_hi < NN) {
                __half2 h = __floats2half2_rn(d[i][j][2] * di_hi, d[i][j][3] * di_hi);
                *(__half2*)&out[(size_t)r_hi * DD + col] = h;
            }
        }
    }
}

// ---------------- layer-1 GEMM: reads x (fp32) directly ----------------
__global__ void __launch_bounds__(512, 2)
k_gemm1(const float* __restrict__ x) {
    extern __shared__ __half sm[];
    int tid = threadIdx.x;
    int row0 = blockIdx.x * 128;

    for (int t = tid; t < 4096; t += 512) {
        int q = t & 31, r = t >> 5;      // q: float4 index within row
        int grow = row0 + r;
        float4 v = make_float4(0.f, 0.f, 0.f, 0.f);
        if (grow < NN) v = ((const float4*)x)[(size_t)grow * 32 + q];
        __half2 p0 = __floats2half2_rn(v.x, v.y);
        __half2 p1 = __floats2half2_rn(v.z, v.w);
        *(uint2*)&sm[AS_OFF + r * ASTR + q * 4] =
            make_uint2(*(uint32_t*)&p0, *(uint32_t*)&p1);
    }
    gemm_core(sm, row0, g_whi, g_wlo, g_h0);
}

// ---------------- aggregate helpers ----------------
__device__ __forceinline__ void add8(float* a, uint4 v) {
    __half2* p = (__half2*)&v;
    #pragma unroll
    for (int k = 0; k < 4; k++) {
        float2 f = __half22float2(p[k]);
        a[2 * k] += f.x;
        a[2 * k + 1] += f.y;
    }
}

// Aggregate one node's 8-float slice (columns hl*8..hl*8+7) from hin.
// Whole warp participates in shfl (two halves, two nodes).
__device__ __forceinline__ void agg_node(const uint4* h4, int node, int lane,
                                         int half, int hl,
                                         const float* __restrict__ bias,
                                         float* a, bool valid) {
    if (valid) {
        uint4 v = h4[(size_t)node * 16 + hl];
        __half2* p = (__half2*)&v;
        #pragma unroll
        for (int k = 0; k < 4; k++) {
            float2 f = __half22float2(p[k]);
            a[2 * k] = f.x;
            a[2 * k + 1] = f.y;
        }
    } else {
        #pragma unroll
        for (int k = 0; k < 8; k++) a[k] = 0.f;
    }

    int s = 0, e = 0;
    if (valid) { s = g_rowptr[node]; e = g_rowptr[node + 1]; }
    int chunks = (e - s + 15) >> 4;
    int cmax = max(chunks, __shfl_xor_sync(0xffffffffu, chunks, 16));

    for (int t = 0; t < cmax; t++) {
        int p = s + t * 16 + hl;
        int idx = (t < chunks && p < e) ? g_csrc[p] : -1;
        #pragma unroll
        for (int u = 0; u < 16; u++) {
            int uu = __shfl_sync(0xffffffffu, idx, (half << 4) + u);
            if (uu >= 0) add8(a, h4[(size_t)uu * 16 + hl]);
        }
    }

    if (valid) {
        float di = g_dinv[node];
        const float4* b4 = (const float4*)bias;
        float4 b0 = b4[hl * 2], b1 = b4[hl * 2 + 1];
        a[0] = fmaxf(fmaf(a[0], di, b0.x), 0.f);
        a[1] = fmaxf(fmaf(a[1], di, b0.y), 0.f);
        a[2] = fmaxf(fmaf(a[2], di, b0.z), 0.f);
        a[3] = fmaxf(fmaf(a[3], di, b0.w), 0.f);
        a[4] = fmaxf(fmaf(a[4], di, b1.x), 0.f);
        a[5] = fmaxf(fmaf(a[5], di, b1.y), 0.f);
        a[6] = fmaxf(fmaf(a[6], di, b1.z), 0.f);
        a[7] = fmaxf(fmaf(a[7], di, b1.w), 0.f);
    }
}

__device__ __forceinline__ uint4 pack8(const float* a) {
    __half2 p0 = __floats2half2_rn(a[0], a[1]);
    __half2 p1 = __floats2half2_rn(a[2], a[3]);
    __half2 p2 = __floats2half2_rn(a[4], a[5]);
    __half2 p3 = __floats2half2_rn(a[6], a[7]);
    return make_uint4(*(uint32_t*)&p0, *(uint32_t*)&p1,
                      *(uint32_t*)&p2, *(uint32_t*)&p3);
}

// ------- fused aggregate + next-layer GEMM: act tile never leaves smem -------
// rw=0: read g_h0, write g_h1.  rw=1: read g_h1, write g_h0.
__global__ void __launch_bounds__(512, 2)
k_fused(int layer, const float* __restrict__ bias, int rw) {
    extern __shared__ __half sm[];
    int tid = threadIdx.x;
    int wid = tid >> 5, lane = tid & 31;
    int half = lane >> 4, hl = lane & 15;
    int row0 = blockIdx.x * 128;
    const uint4* h4 = (const uint4*)(rw ? g_h1 : g_h0);
    __half* out = rw ? g_h0 : g_h1;

    // aggregate phase: 16 warps x 2 nodes x 4 rounds = 128 rows into smem A
    #pragma unroll
    for (int rnd = 0; rnd < 4; rnd++) {
        int r = rnd * 32 + wid * 2 + half;
        int node = row0 + r;
        float a[8];
        agg_node(h4, node, lane, half, hl, bias, a, node < NN);
        *(uint4*)&sm[AS_OFF + r * ASTR + hl * 8] = (node < NN)
            ? pack8(a) : make_uint4(0, 0, 0, 0);
    }
    gemm_core(sm, row0, g_whi + layer * DD * DD, g_wlo + layer * DD * DD, out);
}

// ------- final aggregation (layer 3): g_h0 -> g_act for pooling -------
__global__ void __launch_bounds__(256) k_aggregate(const float* __restrict__ bias) {
    int wid = threadIdx.x >> 5, lane = threadIdx.x & 31;
    int half = lane >> 4, hl = lane & 15;
    int node = blockIdx.x * 16 + wid * 2 + half;   // NN = 16*3125, always valid
    const uint4* h4 = (const uint4*)g_h0;
    float a[8];
    agg_node(h4, node, lane, half, hl, bias, a, true);
    ((uint4*)g_act)[(size_t)node * 16 + hl] = pack8(a);
}

// ---------------- pool (mean per graph) + classifier ----------------
__global__ void __launch_bounds__(128) k_pool_cls(const float* __restrict__ Wc,
                                                  const float* __restrict__ bc,
                                                  const float* __restrict__ Wo,
                                                  const float* __restrict__ bo,
                                                  float* __restrict__ out) {
    __shared__ float pooled[DD];
    __shared__ float zs[HH];
    int g = blockIdx.x, c = threadIdx.x;
    int s = g_gptr[g], e = g_gptr[g + 1];
    float acc = 0.f;
    for (int i = s; i < e; i++)
        acc += __half2float(g_act[(size_t)i * DD + c]);
    pooled[c] = acc / fmaxf((float)(e - s), 1.0f);
    __syncthreads();
    if (c < HH) {
        float z = bc[c];
        #pragma unroll
        for (int dd = 0; dd < DD; dd++) z = fmaf(pooled[dd], Wc[dd * HH + c], z);
        z = fmaxf(z, 0.f);
        zs[c] = z * Wo[c];
    }
    __syncthreads();
    if (c == 0) {
        float r = bo[0];
        #pragma unroll
        for (int h = 0; h < HH; h++) r += zs[h];
        out[g] = r;
    }
}

// ---------------- launch ----------------
extern "C" void kernel_launch(void* const* d_in, const int* in_sizes, int n_in,
                              void* d_out, int out_size) {
    const float* x  = (const float*)d_in[0];
    const int*   ei = (const int*)d_in[1];      // [2, E] int32
    const int*   batch = (const int*)d_in[2];
    const float* W1 = (const float*)d_in[3];
    const float* b1 = (const float*)d_in[4];
    const float* W2 = (const float*)d_in[5];
    const float* b2 = (const float*)d_in[6];
    const float* W3 = (const float*)d_in[7];
    const float* b3 = (const float*)d_in[8];
    const float* Wc = (const float*)d_in[9];
    const float* bc = (const float*)d_in[10];
    const float* Wo = (const float*)d_in[11];
    const float* bo = (const float*)d_in[12];
    float* out = (float*)d_out;

    const int* src = ei;
    const int* dst = ei + EE;

    cudaFuncSetAttribute(k_gemm1, cudaFuncAttributeMaxDynamicSharedMemorySize,
                         GSMEM_BYTES);
    cudaFuncSetAttribute(k_fused, cudaFuncAttributeMaxDynamicSharedMemorySize,
                         GSMEM_BYTES);

    const int NB_N = (NN + 255) / 256;
    const int NB_E = (EE + 255) / 256;

    // graph structure (once per call)
    k_init_nodes<<<NB_N, 256>>>();
    k_hist<<<NB_E, 256>>>(dst);
    k_scan1<<<NB_SCAN, 1024>>>();
    k_scan3_gptr<<<NB_SCAN, 1024>>>(batch);
    k_fill<<<NB_E, 256>>>(src, dst);

    // W conversion (tiny)
    k_convert_w<<<WBLK, 256>>>(W1, W2, W3);

    const int NB_G = (NN + 127) / 128;    // 391 tile blocks
    const int NB_A = NN / 16;             // final aggregate blocks (exact)

    // layer 1 GEMM (reads x directly) -> g_h0
    k_gemm1<<<NB_G, 512, GSMEM_BYTES>>>(x);
    // fused: aggregate(b1) + GEMM W2 : g_h0 -> g_h1
    k_fused<<<NB_G, 512, GSMEM_BYTES>>>(1, b1, 0);
    // fused: aggregate(b2) + GEMM W3 : g_h1 -> g_h0
    k_fused<<<NB_G, 512, GSMEM_BYTES>>>(2, b2, 1);
    // final aggregate(b3): g_h0 -> g_act
    k_aggregate<<<NB_A, 256>>>(b3);

    // pool + classifier
    k_pool_cls<<<GG, 128>>>(Wc, bc, Wo, bo, out);
}

// round 16
// speedup vs baseline: 1.2067x; 1.2067x over previous
#include <cuda_runtime.h>
#include <cuda_bf16.h>
#include <cuda_fp16.h>
#include <cstdint>

// Problem constants (fixed by the dataset)
#define NN 50000
#define EE 800000
#define DD 128
#define HH 64
#define GG 512
#define NB_SCAN ((NN + 1023) / 1024)   // 49

// ---------------- device scratch (static allocation only) ----------------
__device__ __half g_act[(size_t)NN * DD];  // activations: GEMM input (fp16)
__device__ __half g_h[(size_t)NN * DD];    // dinv-scaled GEMM output (fp16)
__device__ float  g_dinv[NN];
__device__ int    g_deg[NN];               // in-degree (zeroed by scan for next replay)
__device__ int    g_fill[NN];              // CSR cursor (zeroed by pool for next replay)
__device__ int    g_rowptr[NN + 1];
__device__ int    g_csrc[EE];
__device__ int    g_bsum[NB_SCAN];
__device__ int    g_gptr[GG + 1];
__device__ unsigned int g_bar;             // monotonic grid-barrier counter
__device__ __half g_whi[3 * DD * DD];      // transposed W fp16 hi: [layer][n][k]
__device__ __half g_wlo[3 * DD * DD];      // fp16 lo (residual): W ~= hi + lo

__device__ __forceinline__ uint32_t smem_u32(const void* p) {
    uint32_t a;
    asm("{ .reg .u64 t; cvta.to.shared.u64 t, %1; cvt.u32.u64 %0, t; }"
        : "=r"(a) : "l"(p));
    return a;
}

// ---------------- prep kernels ----------------
__global__ void k_hist(const int* __restrict__ dst) {
    int e = blockIdx.x * blockDim.x + threadIdx.x;
    if (e < EE) atomicAdd(&g_deg[dst[e]], 1);
}

// grid barrier for exactly NB_SCAN co-resident blocks; monotonic epochs so
// graph replays need no counter reset (all arrivals of replay R precede R+1).
__device__ __forceinline__ void grid_barrier_scan() {
    __syncthreads();
    __threadfence();
    if (threadIdx.x == 0) {
        unsigned my = atomicAdd(&g_bar, 1);
        unsigned target = (my / NB_SCAN + 1) * NB_SCAN;
        while (atomicAdd(&g_bar, 0) < target) { }
    }
    __syncthreads();
}

// fused: local scan of in-degree (+dinv, +deg-rezero) | barrier | global offsets + gptr
__global__ void __launch_bounds__(1024) k_scan_fused(const int* __restrict__ batch) {
    __shared__ int wsum[32];
    int tid = threadIdx.x, lane = tid & 31, wid = tid >> 5;
    int i = blockIdx.x * 1024 + tid;

    // ---- phase A: local inclusive scan of din ----
    int din = (i < NN) ? g_deg[i] : 0;
    if (i < NN) {
        g_dinv[i] = rsqrtf((float)(din + 1));   // +1 self loop
        g_deg[i] = 0;                           // self-clean for next replay
    }
    int x = din;
    #pragma unroll
    for (int off = 1; off < 32; off <<= 1) {
        int y = __shfl_up_sync(0xffffffff, x, off);
        if (lane >= off) x += y;
    }
    if (lane == 31) wsum[wid] = x;
    __syncthreads();
    if (wid == 0) {
        int w = wsum[lane];
        #pragma unroll
        for (int off = 1; off < 32; off <<= 1) {
            int y = __shfl_up_sync(0xffffffff, w, off);
            if (lane >= off) w += y;
        }
        wsum[lane] = w;
    }
    __syncthreads();
    int incl = x + (wid > 0 ? wsum[wid - 1] : 0);
    if (i < NN) g_rowptr[i + 1] = incl;
    if (tid == 1023) g_bsum[blockIdx.x] = incl;

    grid_barrier_scan();

    // ---- phase B: add cross-block offset, graph boundaries ----
    __shared__ int partial[2];
    if (tid < 64) {
        int v = (tid < NB_SCAN && tid < blockIdx.x) ? g_bsum[tid] : 0;
        #pragma unroll
        for (int off = 16; off > 0; off >>= 1)
            v += __shfl_xor_sync(0xffffffffu, v, off);
        if (lane == 0) partial[wid] = v;
    }
    __syncthreads();
    int off = partial[0] + partial[1];
    if (i < NN) {
        g_rowptr[i + 1] += off;
        int b = batch[i];
        int pb = (i > 0) ? batch[i - 1] : -1;
        for (int g = pb + 1; g <= b; g++) g_gptr[g] = i;   // lower_bound boundaries
        if (i == NN - 1)
            for (int g = b + 1; g <= GG; g++) g_gptr[g] = NN;
    }
    if (i == 0) g_rowptr[0] = 0;
}

__global__ void k_fill(const int* __restrict__ src, const int* __restrict__ dst) {
    int e = blockIdx.x * blockDim.x + threadIdx.x;
    if (e >= EE) return;
    int s = src[e], d = dst[e];
    int p = g_rowptr[d] + atomicAdd(&g_fill[d], 1);
    g_csrc[p] = s;
}

// ---- W conversion: hi/lo fp16, transposed [n][k] ----
#define WBLK (3 * DD * DD / 256)             // 192

__global__ void __launch_bounds__(256) k_convert_w(const float* __restrict__ W1,
                                                   const float* __restrict__ W2,
                                                   const float* __restrict__ W3) {
    int idx = blockIdx.x * 256 + threadIdx.x;   // 0 .. 49151
    int layer = idx >> 14;
    int r = idx & 16383;
    int k = r >> 7, n = r & 127;
    const float* W = (layer == 0) ? W1 : (layer == 1) ? W2 : W3;
    float v = W[k * DD + n];                    // coalesced over n
    __half h = __float2half_rn(v);
    __half l = __float2half_rn(v - __half2float(h));
    g_whi[layer * DD * DD + n * DD + k] = h;
    g_wlo[layer * DD * DD + n * DD + k] = l;
}

// ---------------- shared GEMM core ----------------
// smem A tile already filled by caller. Fills B hi/lo, syncs, runs the
// 2-product fp16 mainloop, writes dinv-scaled fp16 rows to g_h.
#define ASTR 136
#define AS_OFF 0
#define BH_OFF (128 * ASTR)
#define BL_OFF (2 * 128 * ASTR)
#define GSMEM_BYTES (3 * 128 * ASTR * 2)   // 104448

__device__ __forceinline__ void ldsm_x4(uint32_t& r0, uint32_t& r1,
                                        uint32_t& r2, uint32_t& r3, uint32_t a) {
    asm volatile("ldmatrix.sync.aligned.m8n8.x4.shared.b16 {%0,%1,%2,%3}, [%4];"
                 : "=r"(r0), "=r"(r1), "=r"(r2), "=r"(r3) : "r"(a));
}

__device__ __forceinline__ void mma_fp16(float* d, const uint32_t* a,
                                         const uint32_t* b) {
    asm volatile(
        "mma.sync.aligned.m16n8k16.row.col.f32.f16.f16.f32 "
        "{%0,%1,%2,%3}, {%4,%5,%6,%7}, {%8,%9}, {%0,%1,%2,%3};"
        : "+f"(d[0]), "+f"(d[1]), "+f"(d[2]), "+f"(d[3])
        : "r"(a[0]), "r"(a[1]), "r"(a[2]), "r"(a[3]), "r"(b[0]), "r"(b[1]));
}

__device__ __forceinline__ void gemm_core(__half* sm, int row0,
                                          const __half* whi, const __half* wlo) {
    int tid = threadIdx.x;
    int wid = tid >> 5, lane = tid & 31;

    for (int t = tid; t < 2048; t += 512) {
        int q = t & 15, n = t >> 4;
        *(uint4*)&sm[BH_OFF + n * ASTR + q * 8] = *(const uint4*)&whi[n * DD + q * 8];
        *(uint4*)&sm[BL_OFF + n * ASTR + q * 8] = *(const uint4*)&wlo[n * DD + q * 8];
    }
    __syncthreads();

    int wm = (wid >> 2) * 32;
    int wn = (wid & 3) * 32;

    float d[2][4][4];
    #pragma unroll
    for (int i = 0; i < 2; i++)
        #pragma unroll
        for (int j = 0; j < 4; j++)
            #pragma unroll
            for (int r = 0; r < 4; r++) d[i][j][r] = 0.f;

    uint32_t sbase = smem_u32(sm);

    #pragma unroll
    for (int kc = 0; kc < 8; kc++) {
        int k0 = kc * 16;
        uint32_t ah[2][4], bh[4][2], bl[4][2];
        #pragma unroll
        for (int i = 0; i < 2; i++) {
            int r = wm + 16 * i + (lane & 15);
            int c = k0 + (lane >> 4) * 8;
            uint32_t ad = sbase + (uint32_t)(AS_OFF + r * ASTR + c) * 2;
            ldsm_x4(ah[i][0], ah[i][1], ah[i][2], ah[i][3], ad);
        }
        #pragma unroll
        for (int jj = 0; jj < 2; jj++) {
            int n = wn + 16 * jj + (lane & 15);
            int c = k0 + (lane >> 4) * 8;
            uint32_t r0, r1, r2, r3;
            uint32_t ad = sbase + (uint32_t)(BH_OFF + n * ASTR + c) * 2;
            ldsm_x4(r0, r1, r2, r3, ad);
            bh[2 * jj][0] = r0; bh[2 * jj + 1][0] = r1;
            bh[2 * jj][1] = r2; bh[2 * jj + 1][1] = r3;
            ad = sbase + (uint32_t)(BL_OFF + n * ASTR + c) * 2;
            ldsm_x4(r0, r1, r2, r3, ad);
            bl[2 * jj][0] = r0; bl[2 * jj + 1][0] = r1;
            bl[2 * jj][1] = r2; bl[2 * jj + 1][1] = r3;
        }
        #pragma unroll
        for (int i = 0; i < 2; i++)
            #pragma unroll
            for (int j = 0; j < 4; j++) {
                mma_fp16(d[i][j], ah[i], bh[j]);
                mma_fp16(d[i][j], ah[i], bl[j]);
            }
    }

    // ---- epilogue: scale by dinv[row], fp32 -> fp16 g_h ----
    int rr = lane >> 2;
    int cc = 2 * (lane & 3);
    #pragma unroll
    for (int i = 0; i < 2; i++) {
        int r_lo = row0 + wm + 16 * i + rr;
        int r_hi = r_lo + 8;
        float di_lo = (r_lo < NN) ? g_dinv[r_lo] : 0.f;
        float di_hi = (r_hi < NN) ? g_dinv[r_hi] : 0.f;
        #pragma unroll
        for (int j = 0; j < 4; j++) {
            int col = wn + 8 * j + cc;
            if (r_lo < NN) {
                __half2 h = __floats2half2_rn(d[i][j][0] * di_lo, d[i][j][1] * di_lo);
                *(__half2*)&g_h[(size_t)r_lo * DD + col] = h;
            }
            if (r_hi < NN) {
                __half2 h = __floats2half2_rn(d[i][j][2] * di_hi, d[i][j][3] * di_hi);
                *(__half2*)&g_h[(size_t)r_hi * DD + col] = h;
            }
        }
    }
}

// ---------------- layer-1 GEMM: reads x (fp32) directly ----------------
__global__ void __launch_bounds__(512, 2)
k_gemm1(const float* __restrict__ x) {
    extern __shared__ __half sm[];
    int tid = threadIdx.x;
    int row0 = blockIdx.x * 128;

    for (int t = tid; t < 4096; t += 512) {
        int q = t & 31, r = t >> 5;      // q: float4 index within row
        int grow = row0 + r;
        float4 v = make_float4(0.f, 0.f, 0.f, 0.f);
        if (grow < NN) v = ((const float4*)x)[(size_t)grow * 32 + q];
        __half2 p0 = __floats2half2_rn(v.x, v.y);
        __half2 p1 = __floats2half2_rn(v.z, v.w);
        *(uint2*)&sm[AS_OFF + r * ASTR + q * 4] =
            make_uint2(*(uint32_t*)&p0, *(uint32_t*)&p1);
    }
    gemm_core(sm, row0, g_whi, g_wlo);
}

// ---------------- layer 2/3 GEMM: reads g_act (fp16) ----------------
__global__ void __launch_bounds__(512, 2)
k_gemm_mma(int layer) {
    extern __shared__ __half sm[];
    int tid = threadIdx.x;
    int row0 = blockIdx.x * 128;

    for (int t = tid; t < 2048; t += 512) {
        int q = t & 15, r = t >> 4;
        int grow = row0 + r;
        uint4 v = make_uint4(0, 0, 0, 0);
        if (grow < NN) v = *(const uint4*)&g_act[(size_t)grow * DD + q * 8];
        *(uint4*)&sm[AS_OFF + r * ASTR + q * 8] = v;
    }
    gemm_core(sm, row0, g_whi + layer * DD * DD, g_wlo + layer * DD * DD);
}

// ------- aggregation: act[d] = relu(dinv[d]*(sum_src h'[s] + h'[d]) + b) -------
// 2 nodes per warp, 16-lane half-warps gather full 256B rows with uint4 loads.
// NN = 50000 = 16 * 3125, so every block's 16 nodes are valid.
__device__ __forceinline__ void add8(float* a, uint4 v) {
    __half2* p = (__half2*)&v;
    #pragma unroll
    for (int k = 0; k < 4; k++) {
        float2 f = __half22float2(p[k]);
        a[2 * k] += f.x;
        a[2 * k + 1] += f.y;
    }
}

__global__ void __launch_bounds__(256) k_aggregate(const float* __restrict__ bias) {
    int wid = threadIdx.x >> 5, lane = threadIdx.x & 31;
    int half = lane >> 4, hl = lane & 15;
    int node = blockIdx.x * 16 + wid * 2 + half;
    const uint4* h4 = (const uint4*)g_h;

    float a[8];
    {   // self term h'[d]
        uint4 v = h4[(size_t)node * 16 + hl];
        __half2* p = (__half2*)&v;
        #pragma unroll
        for (int k = 0; k < 4; k++) {
            float2 f = __half22float2(p[k]);
            a[2 * k] = f.x;
            a[2 * k + 1] = f.y;
        }
    }

    int s = g_rowptr[node], e = g_rowptr[node + 1];
    int chunks = (e - s + 15) >> 4;
    int cmax = max(chunks, __shfl_xor_sync(0xffffffffu, chunks, 16));

    for (int t = 0; t < cmax; t++) {
        int p = s + t * 16 + hl;
        int idx = (t < chunks && p < e) ? g_csrc[p] : -1;
        #pragma unroll
        for (int u = 0; u < 16; u++) {
            int uu = __shfl_sync(0xffffffffu, idx, (half << 4) + u);
            if (uu >= 0) add8(a, h4[(size_t)uu * 16 + hl]);
        }
    }

    float di = g_dinv[node];
    const float4* b4 = (const float4*)bias;
    float4 b0 = b4[hl * 2], b1 = b4[hl * 2 + 1];
    float r0 = fmaxf(fmaf(a[0], di, b0.x), 0.f);
    float r1 = fmaxf(fmaf(a[1], di, b0.y), 0.f);
    float r2 = fmaxf(fmaf(a[2], di, b0.z), 0.f);
    float r3 = fmaxf(fmaf(a[3], di, b0.w), 0.f);
    float r4 = fmaxf(fmaf(a[4], di, b1.x), 0.f);
    float r5 = fmaxf(fmaf(a[5], di, b1.y), 0.f);
    float r6 = fmaxf(fmaf(a[6], di, b1.z), 0.f);
    float r7 = fmaxf(fmaf(a[7], di, b1.w), 0.f);

    __half2 p0 = __floats2half2_rn(r0, r1);
    __half2 p1 = __floats2half2_rn(r2, r3);
    __half2 p2 = __floats2half2_rn(r4, r5);
    __half2 p3 = __floats2half2_rn(r6, r7);
    ((uint4*)g_act)[(size_t)node * 16 + hl] =
        make_uint4(*(uint32_t*)&p0, *(uint32_t*)&p1,
                   *(uint32_t*)&p2, *(uint32_t*)&p3);
}

// ---------------- pool (mean per graph) + classifier + fill-rezero ----------------
__global__ void __launch_bounds__(128) k_pool_cls(const float* __restrict__ Wc,
                                                  const float* __restrict__ bc,
                                                  const float* __restrict__ Wo,
                                                  const float* __restrict__ bo,
                                                  float* __restrict__ out) {
    __shared__ float pooled[DD];
    __shared__ float zs[HH];
    int g = blockIdx.x, c = threadIdx.x;

    // self-clean g_fill for the next graph replay (512*128 threads >= NN)
    int z = g * 128 + c;
    if (z < NN) g_fill[z] = 0;

    int s = g_gptr[g], e = g_gptr[g + 1];
    float acc = 0.f;
    for (int i = s; i < e; i++)
        acc += __half2float(g_act[(size_t)i * DD + c]);
    pooled[c] = acc / fmaxf((float)(e - s), 1.0f);
    __syncthreads();
    if (c < HH) {
        float v = bc[c];
        #pragma unroll
        for (int dd = 0; dd < DD; dd++) v = fmaf(pooled[dd], Wc[dd * HH + c], v);
        v = fmaxf(v, 0.f);
        zs[c] = v * Wo[c];
    }
    __syncthreads();
    if (c == 0) {
        float r = bo[0];
        #pragma unroll
        for (int h = 0; h < HH; h++) r += zs[h];
        out[g] = r;
    }
}

// ---------------- launch ----------------
extern "C" void kernel_launch(void* const* d_in, const int* in_sizes, int n_in,
                              void* d_out, int out_size) {
    const float* x  = (const float*)d_in[0];
    const int*   ei = (const int*)d_in[1];      // [2, E] int32
    const int*   batch = (const int*)d_in[2];
    const float* W1 = (const float*)d_in[3];
    const float* b1 = (const float*)d_in[4];
    const float* W2 = (const float*)d_in[5];
    const float* b2 = (const float*)d_in[6];
    const float* W3 = (const float*)d_in[7];
    const float* b3 = (const float*)d_in[8];
    const float* Wc = (const float*)d_in[9];
    const float* bc = (const float*)d_in[10];
    const float* Wo = (const float*)d_in[11];
    const float* bo = (const float*)d_in[12];
    float* out = (float*)d_out;

    const int* src = ei;
    const int* dst = ei + EE;

    cudaFuncSetAttribute(k_gemm1, cudaFuncAttributeMaxDynamicSharedMemorySize,
                         GSMEM_BYTES);
    cudaFuncSetAttribute(k_gemm_mma, cudaFuncAttributeMaxDynamicSharedMemorySize,
                         GSMEM_BYTES);

    const int NB_E = (EE + 255) / 256;

    // graph structure (once per call); g_deg/g_fill are self-cleaning
    k_hist<<<NB_E, 256>>>(dst);
    k_scan_fused<<<NB_SCAN, 1024>>>(batch);
    k_fill<<<NB_E, 256>>>(src, dst);

    // W conversion (tiny)
    k_convert_w<<<WBLK, 256>>>(W1, W2, W3);

    const int NB_G = (NN + 127) / 128;    // 391 tile blocks
    const int NB_A = NN / 16;             // aggregate blocks (exact)

    // layer 1 (reads x directly)
    k_gemm1<<<NB_G, 512, GSMEM_BYTES>>>(x);
    k_aggregate<<<NB_A, 256>>>(b1);
    // layer 2
    k_gemm_mma<<<NB_G, 512, GSMEM_BYTES>>>(1);
    k_aggregate<<<NB_A, 256>>>(b2);
    // layer 3
    k_gemm_mma<<<NB_G, 512, GSMEM_BYTES>>>(2);
    k_aggregate<<<NB_A, 256>>>(b3);

    // pool + classifier (+ g_fill rezero)
    k_pool_cls<<<GG, 128>>>(Wc, bc, Wo, bo, out);
}